// round 13
// baseline (speedup 1.0000x reference)
#include <cuda_runtime.h>
#include <cstdint>

// Problem constants
#define BB 32
#define SS 2048
#define HH 32
#define NOPE 128
#define VD 128
#define HID 4096
#define QKVN 12288              // 4096 q (compact nope) + 4096 k + 4096 v
#define SCALE 0.08838834764831843f   // 128^-0.5

#define NCHUNK 8
#define CHUNK 256

#define SPLIT1 32               // GEMM1 split-K
#define SPLIT2 32               // GEMM2 split-K

// ---------------- scratch (static device globals; no runtime alloc) -------------
__device__ float g_p1[(size_t)SPLIT1 * 32u * 12288u];   // GEMM1 partials (50 MB)
__device__ float g_qkv[32u * 12288u];            // fused q/k/v projections
__device__ float g_pm[1024 * NCHUNK];            // per-(b,h,chunk) running max
__device__ float g_pl[1024 * NCHUNK];            // per-(b,h,chunk) exp-sum
__device__ float g_pacc[1024 * NCHUNK * 128];    // per-chunk weighted V (4 MB)
__device__ float g_attn[32u * 4096u];            // attention output [B][H*VD]
__device__ float g_p2[(size_t)SPLIT2 * 32u * 4096u];    // GEMM2 partials (16.8 MB)

// packed f32x2 fma (Blackwell sm_100+); doubles fp32 FMA throughput
__device__ __forceinline__ unsigned long long ffma2(unsigned long long a,
                                                    unsigned long long b,
                                                    unsigned long long c) {
    unsigned long long d;
    asm("fma.rn.f32x2 %0, %1, %2, %3;" : "=l"(d) : "l"(a), "l"(b), "l"(c));
    return d;
}
// duplicate a float into both halves of a u64 (for f32x2 B-operand)
__device__ __forceinline__ unsigned long long dupf(float x) {
    unsigned u = __float_as_uint(x);
    unsigned long long r;
    asm("mov.b64 %0, {%1, %2};" : "=l"(r) : "r"(u), "r"(u));
    return r;
}
__device__ __forceinline__ void cp16(uint32_t dst, const float* src) {
    asm volatile("cp.async.cg.shared.global [%0], [%1], 16;" ::"r"(dst),
                 "l"(src)
                 : "memory");
}

// ---------------- prep kernels (also place gemm1 in ncu's profiled slot 4) ------
__global__ void zero_pl_kernel() { g_pl[blockIdx.x * 256 + threadIdx.x] = 0.f; }
__global__ void zero_pm0_kernel() { g_pm[blockIdx.x * 256 + threadIdx.x] = -1e30f; }
__global__ void zero_pm1_kernel() {
    g_pm[4096 + blockIdx.x * 256 + threadIdx.x] = -1e30f;
}

// =====================================================================
// GEMM v6: v4's PROVEN layout (cp.async W + quad-swizzle, broadcast A)
// with the per-thread tile HALVED to 16M x 2N (acc = 16 u64 = 32 regs).
// v4 was register-capped: 128 regs -> 16 warps/SM -> issue 41%. v5's
// layout change regressed (STS conflicts). v6 keeps v4's memory paths
// verbatim and buys occupancy instead: ~70 regs, __launch_bounds__(256,3)
// -> 24 warps/SM. Block tile: BN=256, BM=32 (2 m-halves), BK=16,
// double-buffered smem, cp.async W staging, register-prefetched A.
// MODE 0: W = fused Wq(nope-compact rows)+Wkv virtual rows, -> g_p1.
// MODE 1: W = Wo, A = g_attn, -> g_p2.
// Warp w: N-quadrant (w>>1)*64 (rows wl, wl+32), m-half (w&1)*16.
// =====================================================================
template <int MODE>
__global__ void __launch_bounds__(256, 3) gemm_kernel(
    const float* __restrict__ A, const float* __restrict__ W0,
    const float* __restrict__ W1, int N, int ksteps, float* __restrict__ part) {
    extern __shared__ __align__(16) float smem[];
    float(*Ws)[16] = (float(*)[16])smem;                    // [2*256][16]
    float(*As)[32] = (float(*)[32])(smem + 2 * 256 * 16);   // [2*16][32]

    const int t = threadIdx.x;
    const int w = t >> 5, l = t & 31;
    const int n0 = blockIdx.x * 256;
    const int kbase = blockIdx.y * (ksteps * 16);
    const float* Ap = (MODE == 0) ? A : g_attn;

    const int mh = (w & 1) * 16;          // m-half base (16 rows)
    const int wl = (w >> 1) * 64 + l;     // W rows wl and wl+32

    // W staging: 4 lanes per row (quad wq), rows wr = t>>2 (64/pass, 4 passes)
    const int wr = t >> 2;
    const int wq = t & 3;
    const float* wptr[4];
#pragma unroll
    for (int p = 0; p < 4; p++) {
        int n = n0 + p * 64 + wr;
        const float* row;
        if (MODE == 0)
            row = (n < 4096) ? W0 + (size_t)((n >> 7) * 192 + (n & 127)) * HID
                             : W1 + (size_t)(n - 4096) * HID;
        else
            row = W0 + (size_t)n * HID;
        wptr[p] = row + kbase + 4 * wq;
    }
    const int scol = ((wq ^ ((wr >> 1) & 3)) << 2);

    // A staging: 2 k-values per thread per step (m = t&31, k-pair = (t>>5)*2)
    const int am = t & 31;
    const int ak2 = (t >> 5) * 2;
    const float* aptr = Ap + (size_t)am * HID + kbase + ak2;

    unsigned long long accE[8], accO[8];   // m-pairs within the m-half
#pragma unroll
    for (int p = 0; p < 8; p++) {
        accE[p] = 0ull;
        accO[p] = 0ull;
    }

    // prologue: step 0 W via cp.async (group 0), A via LDG
#pragma unroll
    for (int p = 0; p < 4; p++) {
        uint32_t dst =
            (uint32_t)__cvta_generic_to_shared(&Ws[p * 64 + wr][scol]);
        cp16(dst, wptr[p]);
    }
    asm volatile("cp.async.commit_group;" ::: "memory");
    float2 aA = *(const float2*)aptr;

    for (int ks = 0; ks < ksteps; ks++) {
        const int buf = ks & 1;
        float2 aN = aA;
        if (ks + 1 < ksteps) {
            const int nb = 1 - buf;
#pragma unroll
            for (int p = 0; p < 4; p++) {
                uint32_t dst = (uint32_t)__cvta_generic_to_shared(
                    &Ws[nb * 256 + p * 64 + wr][scol]);
                cp16(dst, wptr[p] + (ks + 1) * 16);
            }
            asm volatile("cp.async.commit_group;" ::: "memory");
            aN = *(const float2*)(aptr + (ks + 1) * 16);
        }
        // stage this step's A (regs -> smem)
        As[buf * 16 + ak2][am] = aA.x;
        As[buf * 16 + ak2 + 1][am] = aA.y;
        if (ks + 1 < ksteps)
            asm volatile("cp.async.wait_group 1;" ::: "memory");
        else
            asm volatile("cp.async.wait_group 0;" ::: "memory");
        __syncthreads();
        aA = aN;

        // ---- compute 16 kk ----
        const float(*Wb)[16] = Ws + buf * 256;
        const float(*Ab)[32] = As + buf * 16;
#pragma unroll
        for (int q = 0; q < 4; q++) {
            const int c = ((q ^ ((wl >> 1) & 3)) << 2);   // same for wl+32
            float4 wEq = *(const float4*)&Wb[wl][c];
            float4 wOq = *(const float4*)&Wb[wl + 32][c];
#pragma unroll
            for (int i = 0; i < 4; i++) {
                unsigned long long w2E = dupf((&wEq.x)[i]);
                unsigned long long w2O = dupf((&wOq.x)[i]);
                const ulonglong2* ap =
                    (const ulonglong2*)&Ab[4 * q + i][mh];
#pragma unroll
                for (int j = 0; j < 4; j++) {
                    ulonglong2 v = ap[j];   // m-pairs (4j, 4j+1), (4j+2, 4j+3)
                    accE[2 * j] = ffma2(v.x, w2E, accE[2 * j]);
                    accE[2 * j + 1] = ffma2(v.y, w2E, accE[2 * j + 1]);
                    accO[2 * j] = ffma2(v.x, w2O, accO[2 * j]);
                    accO[2 * j + 1] = ffma2(v.y, w2O, accO[2 * j + 1]);
                }
            }
        }
        __syncthreads();   // compute done before next iter overwrites buf
    }

    // ---- epilogue ----
    const int nE = n0 + wl, nO = nE + 32;
    float* bE = part + (size_t)blockIdx.y * 32 * N + nE;
    float* bO = part + (size_t)blockIdx.y * 32 * N + nO;
#pragma unroll
    for (int p = 0; p < 8; p++) {
        int m0 = mh + 2 * p;
        bE[(size_t)m0 * N] = __uint_as_float((unsigned)(accE[p] & 0xffffffffull));
        bE[(size_t)(m0 + 1) * N] = __uint_as_float((unsigned)(accE[p] >> 32));
        bO[(size_t)m0 * N] = __uint_as_float((unsigned)(accO[p] & 0xffffffffull));
        bO[(size_t)(m0 + 1) * N] = __uint_as_float((unsigned)(accO[p] >> 32));
    }
}

// sum the SPLIT1 GEMM1 split-K partials -> g_qkv
__global__ void reduce_qkv_kernel() {
    int i = blockIdx.x * 256 + threadIdx.x;   // 393216 total
    float s = 0.f;
#pragma unroll
    for (int c = 0; c < SPLIT1; c++) s += g_p1[(size_t)c * 393216 + i];
    g_qkv[i] = s;
}

// =====================================================================
// Flash-decoding attention partial (AT THE MEMORY WALL: 80% DRAM, ~96%
// of the 6.35 TB/s LTS cap — unchanged). One block per (b,h,chunk).
// =====================================================================
__global__ void __launch_bounds__(256) attn_partial_kernel(
    const float* __restrict__ k_cache, const float* __restrict__ v_cache,
    const int* __restrict__ positions) {
    const int bh = blockIdx.x;
    const int c = blockIdx.y;
    const int b = bh >> 5, h = bh & 31;
    const int t = threadIdx.x, lane = t & 31, w = t >> 5;
    const int pos = positions[b];
    const int L = pos + 1;
    const int s0 = c * CHUNK;
    const int len = min(CHUNK, L - s0);
    const int pidx = bh * NCHUNK + c;
    if (len <= 0) return;   // g_pl pre-zeroed by prep kernel

    __shared__ float sc[CHUNK];
    __shared__ float red[256];
    __shared__ float redw[8];
    __shared__ float s_m, s_l;

    const float* qb = g_qkv + b * QKVN + h * 128;
    const float4 q4 = *(const float4*)(qb + lane * 4);
    const float* knew = g_qkv + b * QKVN + 4096 + h * 128;
    const float* kbasep = k_cache + (size_t)b * SS * (HH * 128) + h * 128;

    for (int sl = 4 * w; sl < len; sl += 32) {
        float4 kv[4];
        float dd[4];
#pragma unroll
        for (int i = 0; i < 4; i++) {
            int sli = sl + i;
            int s = s0 + sli;
            const float* kp = (sli < len)
                                  ? ((s == pos) ? knew
                                                : (kbasep + (size_t)s * 4096))
                                  : knew;   // safe dummy
            kv[i] = *(const float4*)(kp + lane * 4);
        }
#pragma unroll
        for (int i = 0; i < 4; i++)
            dd[i] = kv[i].x * q4.x + kv[i].y * q4.y + kv[i].z * q4.z +
                    kv[i].w * q4.w;
#pragma unroll
        for (int o = 16; o; o >>= 1) {
#pragma unroll
            for (int i = 0; i < 4; i++)
                dd[i] += __shfl_xor_sync(0xffffffffu, dd[i], o);
        }
        if (lane == 0) {
#pragma unroll
            for (int i = 0; i < 4; i++)
                if (sl + i < len) sc[sl + i] = dd[i] * SCALE;
        }
    }
    __syncthreads();

    float lm = (t < len) ? sc[t] : -1e30f;
#pragma unroll
    for (int o = 16; o; o >>= 1) lm = fmaxf(lm, __shfl_xor_sync(0xffffffffu, lm, o));
    if (lane == 0) redw[w] = lm;
    __syncthreads();
    if (t == 0) {
        float m = redw[0];
#pragma unroll
        for (int i = 1; i < 8; i++) m = fmaxf(m, redw[i]);
        s_m = m;
    }
    __syncthreads();
    const float m = s_m;
    float ls = 0.f;
    if (t < len) {
        float p = __expf(sc[t] - m);
        sc[t] = p;
        ls = p;
    }
#pragma unroll
    for (int o = 16; o; o >>= 1) ls += __shfl_xor_sync(0xffffffffu, ls, o);
    if (lane == 0) redw[w] = ls;
    __syncthreads();
    if (t == 0) {
        float l = 0.f;
#pragma unroll
        for (int i = 0; i < 8; i++) l += redw[i];
        s_l = l;
    }
    __syncthreads();

    const float* vnew = g_qkv + b * QKVN + 8192 + h * 128;
    const float* vbasep = v_cache + (size_t)b * SS * (HH * 128) + h * 128;
    const int d = t & 127;
    const int half = t >> 7;
    float acc = 0.f;
#pragma unroll 8
    for (int sl = half; sl < len; sl += 2) {
        int s = s0 + sl;
        const float* vr = (s == pos) ? vnew : (vbasep + (size_t)s * 4096);
        acc += sc[sl] * vr[d];
    }
    red[t] = acc;
    __syncthreads();
    if (t < 128) g_pacc[(size_t)pidx * 128 + t] = red[t] + red[t + 128];
    if (t == 0) {
        g_pm[pidx] = m;
        g_pl[pidx] = s_l;
    }
}

// combine the <=8 chunk partials per (b,h) -> g_attn[b][h*VD+d]
__global__ void __launch_bounds__(128) attn_combine_kernel() {
    const int bh = blockIdx.x;
    const int d = threadIdx.x;
    float M = -1e30f;
#pragma unroll
    for (int c = 0; c < NCHUNK; c++) {
        float l = g_pl[bh * NCHUNK + c];
        if (l > 0.f) M = fmaxf(M, g_pm[bh * NCHUNK + c]);
    }
    float L = 0.f, o = 0.f;
#pragma unroll
    for (int c = 0; c < NCHUNK; c++) {
        float l = g_pl[bh * NCHUNK + c];
        if (l > 0.f) {
            float wgt = __expf(g_pm[bh * NCHUNK + c] - M);
            L += l * wgt;
            o += g_pacc[(size_t)(bh * NCHUNK + c) * 128 + d] * wgt;
        }
    }
    const int b = bh >> 5, h = bh & 31;
    g_attn[b * 4096 + h * 128 + d] = o / L;
}

// sum the SPLIT2 GEMM2 split-K partials -> final output
__global__ void reduce_out_kernel(float* __restrict__ out) {
    int i = blockIdx.x * 256 + threadIdx.x;   // 131072 total
    float s = 0.f;
#pragma unroll
    for (int c = 0; c < SPLIT2; c++) s += g_p2[(size_t)c * 131072 + i];
    out[i] = s;
}

extern "C" void kernel_launch(void* const* d_in, const int* in_sizes, int n_in,
                              void* d_out, int out_size) {
    const float* hs = (const float*)d_in[0];
    const int* positions = (const int*)d_in[1];
    const float* k_cache = (const float*)d_in[2];
    const float* v_cache = (const float*)d_in[3];
    const float* Wq = (const float*)d_in[4];
    const float* Wkv = (const float*)d_in[5];
    const float* Wo = (const float*)d_in[6];
    float* out = (float*)d_out;

    float* p1;
    cudaGetSymbolAddress((void**)&p1, g_p1);
    float* p2;
    cudaGetSymbolAddress((void**)&p2, g_p2);

    const int SMEM_BYTES = (2 * 256 * 16 + 2 * 16 * 32) * 4;   // 36864
    cudaFuncSetAttribute(gemm_kernel<0>,
                         cudaFuncAttributeMaxDynamicSharedMemorySize, SMEM_BYTES);
    cudaFuncSetAttribute(gemm_kernel<1>,
                         cudaFuncAttributeMaxDynamicSharedMemorySize, SMEM_BYTES);

    // prep (slots 1-3): zero attention stats; puts gemm1 in profiled slot 4
    zero_pl_kernel<<<32, 256>>>();
    zero_pm0_kernel<<<16, 256>>>();
    zero_pm1_kernel<<<16, 256>>>();
    // 1) fused q(nope)/k/v projection: 48 N-tiles x split-K 32 (8 k-steps)
    gemm_kernel<0><<<dim3(48, SPLIT1), 256, SMEM_BYTES>>>(hs, Wq, Wkv, QKVN, 8,
                                                          p1);
    reduce_qkv_kernel<<<1536, 256>>>();
    // 2) flash-decoding attention partials
    attn_partial_kernel<<<dim3(1024, NCHUNK), 256>>>(k_cache, v_cache, positions);
    attn_combine_kernel<<<1024, 128>>>();
    // 3) output projection: 16 N-tiles x split-K 32 (8 k-steps)
    gemm_kernel<1><<<dim3(16, SPLIT2), 256, SMEM_BYTES>>>(nullptr, Wo, nullptr,
                                                          HID, 8, p2);
    reduce_out_kernel<<<512, 256>>>(out);
}

// round 14
// speedup vs baseline: 1.1862x; 1.1862x over previous
#include <cuda_runtime.h>
#include <cstdint>

// Problem constants
#define BB 32
#define SS 2048
#define HH 32
#define NOPE 128
#define VD 128
#define HID 4096
#define QKVN 12288              // 4096 q (compact nope) + 4096 k + 4096 v
#define SCALE 0.08838834764831843f   // 128^-0.5

#define NCHUNK 8
#define CHUNK 256

#define SPLIT1 16               // GEMM1 split-K
#define SPLIT2 16               // GEMM2 split-K

// ---------------- scratch (static device globals; no runtime alloc) -------------
__device__ float g_p1[(size_t)SPLIT1 * 32u * 12288u];   // GEMM1 partials (25 MB)
__device__ float g_qkv[32u * 12288u];            // fused q/k/v projections
__device__ float g_pm[1024 * NCHUNK];            // per-(b,h,chunk) running max
__device__ float g_pl[1024 * NCHUNK];            // per-(b,h,chunk) exp-sum
__device__ float g_pacc[1024 * NCHUNK * 128];    // per-chunk weighted V (4 MB)
__device__ float g_attn[32u * 4096u];            // attention output [B][H*VD]
__device__ float g_p2[(size_t)SPLIT2 * 32u * 4096u];    // GEMM2 partials (8.4 MB)

// ---------------- prep kernels (also place gemm1 in ncu's profiled slot 4) ------
__global__ void zero_pl_kernel() { g_pl[blockIdx.x * 256 + threadIdx.x] = 0.f; }
__global__ void zero_pm0_kernel() { g_pm[blockIdx.x * 256 + threadIdx.x] = -1e30f; }
__global__ void zero_pm1_kernel() {
    g_pm[4096 + blockIdx.x * 256 + threadIdx.x] = -1e30f;
}

// bf16x2 pack: result = {hi: b, lo: a}  (first PTX source -> high half)
__device__ __forceinline__ unsigned bf16x2(float hi, float lo) {
    unsigned d;
    asm("cvt.rn.bf16x2.f32 %0, %1, %2;" : "=r"(d) : "f"(hi), "f"(lo));
    return d;
}
// split (x0, x1) -> packed hi bf16x2 {x1,x0} and packed lo residual bf16x2
__device__ __forceinline__ void split2(float x0, float x1, unsigned& hi,
                                       unsigned& lo) {
    hi = bf16x2(x1, x0);
    float h0 = __uint_as_float(hi << 16);
    float h1 = __uint_as_float(hi & 0xFFFF0000u);
    lo = bf16x2(x1 - h1, x0 - h0);
}
// mma.sync m16n8k16 bf16 -> f32 accumulate in place
#define MMA16816(D, Av, Bv)                                                  \
    asm volatile(                                                            \
        "mma.sync.aligned.m16n8k16.row.col.f32.bf16.bf16.f32 "               \
        "{%0,%1,%2,%3}, {%4,%5,%6,%7}, {%8,%9}, {%0,%1,%2,%3};"              \
        : "+f"(D[0]), "+f"(D[1]), "+f"(D[2]), "+f"(D[3])                     \
        : "r"(Av.x), "r"(Av.y), "r"(Av.z), "r"(Av.w), "r"(Bv.x), "r"(Bv.y))

// =====================================================================
// GEMM v7 (tensor-core): C[32][N] = A[32][4096] @ W[N][4096]^T, split-K.
// fp32 SIMT hit its hard rate floor (~94us = scalar FMA rate; f32x2 is
// half-rate). v7 moves the FLOPs to the HMMA pipe: each fp32 is split
// into bf16 hi + bf16 lo(residual); 3 products (WhiAhi + WhiAlo + WloAhi)
// accumulate in fp32 via mma.sync.m16n8k16 (rel err ~1e-5).
// Staging converts in registers and stores FRAGMENT-ORDERED smem so
// compute loads are conflict-free LDS.128/LDS.64, no shuffles.
// Block: 256 thr = 8 warps; tile M=32 x BN=128 x BK=32 per step.
// Warp w owns ntiles {2w, 2w+1} (16 n-cols). 12 MMA per k16 per warp.
// MODE 0: W = fused Wq(nope-compact rows)+Wkv virtual rows, -> g_p1.
// MODE 1: W = Wo, A = g_attn, -> g_p2.
// =====================================================================
template <int MODE>
__global__ void __launch_bounds__(256, 3) gemm_kernel(
    const float* __restrict__ A, const float* __restrict__ W0,
    const float* __restrict__ W1, int N, int ksteps, float* __restrict__ part) {
    // Wf[nt(16)][k16(2)][hl(2)][lane(32)][breg(2)] u32 = 4096 u32 (16 KB)
    // Af[mt(2)][k16(2)][hl(2)][lane(32)][areg(4)] u32 = 1024 u32 (4 KB)
    __shared__ __align__(16) unsigned Wf[4096];
    __shared__ __align__(16) unsigned Af[1024];

    const int t = threadIdx.x;
    const int w = t >> 5, l = t & 31;
    const int n0 = blockIdx.x * 128;
    const int kbase = blockIdx.y * (ksteps * 32);
    const float* Ap = (MODE == 0) ? A : g_attn;

    // ---- staging assignments (fixed n/m, k advances) ----
    // W: pass p: n = p*32 + (t>>3), k-quad kk = (t&7)*4
    const int wn = t >> 3;
    const int wkk = (t & 7) * 4;
    const float* wptr[4];
#pragma unroll
    for (int p = 0; p < 4; p++) {
        int n = n0 + p * 32 + wn;
        const float* row;
        if (MODE == 0)
            row = (n < 4096) ? W0 + (size_t)((n >> 7) * 192 + (n & 127)) * HID
                             : W1 + (size_t)(n - 4096) * HID;
        else
            row = W0 + (size_t)n * HID;
        wptr[p] = row + kbase + wkk;
    }
    // W frag STS offsets (constant per thread, per pass add ntile term)
    const int wk16 = wkk >> 4;
    const int wbreg = (wkk & 15) >> 3;
    const int wpidx = (wkk & 7) >> 1;   // pair-col of (kk,kk+1); +1 for (kk+2,kk+3)
    // A: m = t>>3, same k-quad
    const int am = t >> 3;
    const float* aptr = Ap + (size_t)am * HID + kbase + wkk;
    const int amt = am >> 4;
    const int aareg = ((am >> 3) & 1) + 2 * wbreg;   // row-half + k-half
    const int alane = 4 * (am & 7) + wpidx;

    float acc[2][2][4];   // [mt][nt][c0..c3]
#pragma unroll
    for (int i = 0; i < 2; i++)
#pragma unroll
        for (int j = 0; j < 2; j++)
#pragma unroll
            for (int c = 0; c < 4; c++) acc[i][j][c] = 0.f;

    for (int ks = 0; ks < ksteps; ks++) {
        const int kofs = ks * 32;
        __syncthreads();   // previous compute done before overwriting frags

        // ---- stage W: 4 passes, convert + fragment-ordered STS ----
#pragma unroll
        for (int p = 0; p < 4; p++) {
            float4 v = *(const float4*)(wptr[p] + kofs);
            unsigned hi0, lo0, hi1, lo1;
            split2(v.x, v.y, hi0, lo0);
            split2(v.z, v.w, hi1, lo1);
            int n = p * 32 + wn;
            int nt = n >> 3;
            int lane0 = 4 * (n & 7) + wpidx;
            unsigned* baseh = Wf + (((nt * 2 + wk16) * 2 + 0) * 32) * 2 + wbreg;
            unsigned* basel = Wf + (((nt * 2 + wk16) * 2 + 1) * 32) * 2 + wbreg;
            baseh[lane0 * 2] = hi0;
            baseh[(lane0 + 1) * 2] = hi1;
            basel[lane0 * 2] = lo0;
            basel[(lane0 + 1) * 2] = lo1;
        }
        // ---- stage A: 1 pass ----
        {
            float4 v = *(const float4*)(aptr + kofs);
            unsigned hi0, lo0, hi1, lo1;
            split2(v.x, v.y, hi0, lo0);
            split2(v.z, v.w, hi1, lo1);
            unsigned* baseh =
                Af + (((amt * 2 + wk16) * 2 + 0) * 32) * 4 + aareg;
            unsigned* basel =
                Af + (((amt * 2 + wk16) * 2 + 1) * 32) * 4 + aareg;
            baseh[alane * 4] = hi0;
            baseh[(alane + 1) * 4] = hi1;
            basel[alane * 4] = lo0;
            basel[(alane + 1) * 4] = lo1;
        }
        __syncthreads();

        // ---- compute: 2 k16 x (2 mt x 2 nt x 3 products) ----
#pragma unroll
        for (int k16 = 0; k16 < 2; k16++) {
            uint4 Ah0 = *(const uint4*)(Af + (((0 * 2 + k16) * 2 + 0) * 32 + l) * 4);
            uint4 Al0 = *(const uint4*)(Af + (((0 * 2 + k16) * 2 + 1) * 32 + l) * 4);
            uint4 Ah1 = *(const uint4*)(Af + (((1 * 2 + k16) * 2 + 0) * 32 + l) * 4);
            uint4 Al1 = *(const uint4*)(Af + (((1 * 2 + k16) * 2 + 1) * 32 + l) * 4);
            uint2 Bh0 = *(const uint2*)(Wf + ((((2 * w) * 2 + k16) * 2 + 0) * 32 + l) * 2);
            uint2 Bl0 = *(const uint2*)(Wf + ((((2 * w) * 2 + k16) * 2 + 1) * 32 + l) * 2);
            uint2 Bh1 = *(const uint2*)(Wf + ((((2 * w + 1) * 2 + k16) * 2 + 0) * 32 + l) * 2);
            uint2 Bl1 = *(const uint2*)(Wf + ((((2 * w + 1) * 2 + k16) * 2 + 1) * 32 + l) * 2);
            MMA16816(acc[0][0], Ah0, Bh0);
            MMA16816(acc[0][1], Ah0, Bh1);
            MMA16816(acc[1][0], Ah1, Bh0);
            MMA16816(acc[1][1], Ah1, Bh1);
            MMA16816(acc[0][0], Al0, Bh0);
            MMA16816(acc[0][1], Al0, Bh1);
            MMA16816(acc[1][0], Al1, Bh0);
            MMA16816(acc[1][1], Al1, Bh1);
            MMA16816(acc[0][0], Ah0, Bl0);
            MMA16816(acc[0][1], Ah0, Bl1);
            MMA16816(acc[1][0], Ah1, Bl0);
            MMA16816(acc[1][1], Ah1, Bl1);
        }
    }

    // ---- epilogue: C[mt][nt] lane map: rows l/4, l/4+8; cols 2(l%4)+{0,1} ----
    float* pbase = part + (size_t)blockIdx.y * 32 * N;
#pragma unroll
    for (int mt = 0; mt < 2; mt++)
#pragma unroll
        for (int nt = 0; nt < 2; nt++) {
            int col = n0 + w * 16 + nt * 8 + 2 * (l & 3);
            int r0 = mt * 16 + (l >> 2);
            *(float2*)(pbase + (size_t)r0 * N + col) =
                make_float2(acc[mt][nt][0], acc[mt][nt][1]);
            *(float2*)(pbase + (size_t)(r0 + 8) * N + col) =
                make_float2(acc[mt][nt][2], acc[mt][nt][3]);
        }
}

// sum the SPLIT1 GEMM1 split-K partials -> g_qkv
__global__ void reduce_qkv_kernel() {
    int i = blockIdx.x * 256 + threadIdx.x;   // 393216 total
    float s = 0.f;
#pragma unroll
    for (int c = 0; c < SPLIT1; c++) s += g_p1[(size_t)c * 393216 + i];
    g_qkv[i] = s;
}

// =====================================================================
// Flash-decoding attention partial (AT THE MEMORY WALL: 80% DRAM, ~96%
// of the 6.35 TB/s LTS cap — unchanged). One block per (b,h,chunk).
// =====================================================================
__global__ void __launch_bounds__(256) attn_partial_kernel(
    const float* __restrict__ k_cache, const float* __restrict__ v_cache,
    const int* __restrict__ positions) {
    const int bh = blockIdx.x;
    const int c = blockIdx.y;
    const int b = bh >> 5, h = bh & 31;
    const int t = threadIdx.x, lane = t & 31, w = t >> 5;
    const int pos = positions[b];
    const int L = pos + 1;
    const int s0 = c * CHUNK;
    const int len = min(CHUNK, L - s0);
    const int pidx = bh * NCHUNK + c;
    if (len <= 0) return;   // g_pl pre-zeroed by prep kernel

    __shared__ float sc[CHUNK];
    __shared__ float red[256];
    __shared__ float redw[8];
    __shared__ float s_m, s_l;

    const float* qb = g_qkv + b * QKVN + h * 128;
    const float4 q4 = *(const float4*)(qb + lane * 4);
    const float* knew = g_qkv + b * QKVN + 4096 + h * 128;
    const float* kbasep = k_cache + (size_t)b * SS * (HH * 128) + h * 128;

    for (int sl = 4 * w; sl < len; sl += 32) {
        float4 kv[4];
        float dd[4];
#pragma unroll
        for (int i = 0; i < 4; i++) {
            int sli = sl + i;
            int s = s0 + sli;
            const float* kp = (sli < len)
                                  ? ((s == pos) ? knew
                                                : (kbasep + (size_t)s * 4096))
                                  : knew;   // safe dummy
            kv[i] = *(const float4*)(kp + lane * 4);
        }
#pragma unroll
        for (int i = 0; i < 4; i++)
            dd[i] = kv[i].x * q4.x + kv[i].y * q4.y + kv[i].z * q4.z +
                    kv[i].w * q4.w;
#pragma unroll
        for (int o = 16; o; o >>= 1) {
#pragma unroll
            for (int i = 0; i < 4; i++)
                dd[i] += __shfl_xor_sync(0xffffffffu, dd[i], o);
        }
        if (lane == 0) {
#pragma unroll
            for (int i = 0; i < 4; i++)
                if (sl + i < len) sc[sl + i] = dd[i] * SCALE;
        }
    }
    __syncthreads();

    float lm = (t < len) ? sc[t] : -1e30f;
#pragma unroll
    for (int o = 16; o; o >>= 1) lm = fmaxf(lm, __shfl_xor_sync(0xffffffffu, lm, o));
    if (lane == 0) redw[w] = lm;
    __syncthreads();
    if (t == 0) {
        float m = redw[0];
#pragma unroll
        for (int i = 1; i < 8; i++) m = fmaxf(m, redw[i]);
        s_m = m;
    }
    __syncthreads();
    const float m = s_m;
    float ls = 0.f;
    if (t < len) {
        float p = __expf(sc[t] - m);
        sc[t] = p;
        ls = p;
    }
#pragma unroll
    for (int o = 16; o; o >>= 1) ls += __shfl_xor_sync(0xffffffffu, ls, o);
    if (lane == 0) redw[w] = ls;
    __syncthreads();
    if (t == 0) {
        float l = 0.f;
#pragma unroll
        for (int i = 0; i < 8; i++) l += redw[i];
        s_l = l;
    }
    __syncthreads();

    const float* vnew = g_qkv + b * QKVN + 8192 + h * 128;
    const float* vbasep = v_cache + (size_t)b * SS * (HH * 128) + h * 128;
    const int d = t & 127;
    const int half = t >> 7;
    float acc = 0.f;
#pragma unroll 8
    for (int sl = half; sl < len; sl += 2) {
        int s = s0 + sl;
        const float* vr = (s == pos) ? vnew : (vbasep + (size_t)s * 4096);
        acc += sc[sl] * vr[d];
    }
    red[t] = acc;
    __syncthreads();
    if (t < 128) g_pacc[(size_t)pidx * 128 + t] = red[t] + red[t + 128];
    if (t == 0) {
        g_pm[pidx] = m;
        g_pl[pidx] = s_l;
    }
}

// combine the <=8 chunk partials per (b,h) -> g_attn[b][h*VD+d]
__global__ void __launch_bounds__(128) attn_combine_kernel() {
    const int bh = blockIdx.x;
    const int d = threadIdx.x;
    float M = -1e30f;
#pragma unroll
    for (int c = 0; c < NCHUNK; c++) {
        float l = g_pl[bh * NCHUNK + c];
        if (l > 0.f) M = fmaxf(M, g_pm[bh * NCHUNK + c]);
    }
    float L = 0.f, o = 0.f;
#pragma unroll
    for (int c = 0; c < NCHUNK; c++) {
        float l = g_pl[bh * NCHUNK + c];
        if (l > 0.f) {
            float wgt = __expf(g_pm[bh * NCHUNK + c] - M);
            L += l * wgt;
            o += g_pacc[(size_t)(bh * NCHUNK + c) * 128 + d] * wgt;
        }
    }
    const int b = bh >> 5, h = bh & 31;
    g_attn[b * 4096 + h * 128 + d] = o / L;
}

// sum the SPLIT2 GEMM2 split-K partials -> final output
__global__ void reduce_out_kernel(float* __restrict__ out) {
    int i = blockIdx.x * 256 + threadIdx.x;   // 131072 total
    float s = 0.f;
#pragma unroll
    for (int c = 0; c < SPLIT2; c++) s += g_p2[(size_t)c * 131072 + i];
    out[i] = s;
}

extern "C" void kernel_launch(void* const* d_in, const int* in_sizes, int n_in,
                              void* d_out, int out_size) {
    const float* hs = (const float*)d_in[0];
    const int* positions = (const int*)d_in[1];
    const float* k_cache = (const float*)d_in[2];
    const float* v_cache = (const float*)d_in[3];
    const float* Wq = (const float*)d_in[4];
    const float* Wkv = (const float*)d_in[5];
    const float* Wo = (const float*)d_in[6];
    float* out = (float*)d_out;

    float* p1;
    cudaGetSymbolAddress((void**)&p1, g_p1);
    float* p2;
    cudaGetSymbolAddress((void**)&p2, g_p2);

    // prep (slots 1-3): zero attention stats; puts gemm1 in profiled slot 4
    zero_pl_kernel<<<32, 256>>>();
    zero_pm0_kernel<<<16, 256>>>();
    zero_pm1_kernel<<<16, 256>>>();
    // 1) fused q(nope)/k/v projection: 96 N-tiles x split-K 16 (8 k-steps)
    gemm_kernel<0><<<dim3(96, SPLIT1), 256>>>(hs, Wq, Wkv, QKVN, 8, p1);
    reduce_qkv_kernel<<<1536, 256>>>();
    // 2) flash-decoding attention partials
    attn_partial_kernel<<<dim3(1024, NCHUNK), 256>>>(k_cache, v_cache, positions);
    attn_combine_kernel<<<1024, 128>>>();
    // 3) output projection: 32 N-tiles x split-K 16 (8 k-steps)
    gemm_kernel<1><<<dim3(32, SPLIT2), 256>>>(nullptr, Wo, nullptr, HID, 8, p2);
    reduce_out_kernel<<<512, 256>>>(out);
}

// round 15
// speedup vs baseline: 1.2229x; 1.0310x over previous
#include <cuda_runtime.h>
#include <cstdint>

// Problem constants
#define BB 32
#define SS 2048
#define HH 32
#define NOPE 128
#define VD 128
#define HID 4096
#define QKVN 12288              // 4096 q (compact nope) + 4096 k + 4096 v
#define SCALE 0.08838834764831843f   // 128^-0.5

#define NCHUNK 8
#define CHUNK 256

#define SPLIT1 16               // GEMM1 split-K
#define SPLIT2 16               // GEMM2 split-K

// ---------------- scratch (static device globals; no runtime alloc) -------------
__device__ float g_p1[(size_t)SPLIT1 * 32u * 12288u];   // GEMM1 partials (25 MB)
__device__ float g_qkv[32u * 12288u];            // fused q/k/v projections
__device__ float g_pm[1024 * NCHUNK];            // per-(b,h,chunk) running max
__device__ float g_pl[1024 * NCHUNK];            // per-(b,h,chunk) exp-sum
__device__ float g_pacc[1024 * NCHUNK * 128];    // per-chunk weighted V (4 MB)
__device__ float g_attn[32u * 4096u];            // attention output [B][H*VD]
__device__ float g_p2[(size_t)SPLIT2 * 32u * 4096u];    // GEMM2 partials (8.4 MB)

// ---------------- prep kernels (also place gemm1 in ncu's profiled slot 4) ------
__global__ void zero_pl_kernel() { g_pl[blockIdx.x * 256 + threadIdx.x] = 0.f; }
__global__ void zero_pm0_kernel() { g_pm[blockIdx.x * 256 + threadIdx.x] = -1e30f; }
__global__ void zero_pm1_kernel() {
    g_pm[4096 + blockIdx.x * 256 + threadIdx.x] = -1e30f;
}

// bf16x2 pack: result = {hi: b, lo: a}  (first PTX source -> high half)
__device__ __forceinline__ unsigned bf16x2(float hi, float lo) {
    unsigned d;
    asm("cvt.rn.bf16x2.f32 %0, %1, %2;" : "=r"(d) : "f"(hi), "f"(lo));
    return d;
}
// split (x0, x1) -> packed hi bf16x2 {x1,x0} and packed lo residual bf16x2
__device__ __forceinline__ void split2(float x0, float x1, unsigned& hi,
                                       unsigned& lo) {
    hi = bf16x2(x1, x0);
    float h0 = __uint_as_float(hi << 16);
    float h1 = __uint_as_float(hi & 0xFFFF0000u);
    lo = bf16x2(x1 - h1, x0 - h0);
}
// mma.sync m16n8k16 bf16 -> f32 accumulate in place
#define MMA16816(D, Av, Bv)                                                  \
    asm volatile(                                                            \
        "mma.sync.aligned.m16n8k16.row.col.f32.bf16.bf16.f32 "               \
        "{%0,%1,%2,%3}, {%4,%5,%6,%7}, {%8,%9}, {%0,%1,%2,%3};"              \
        : "+f"(D[0]), "+f"(D[1]), "+f"(D[2]), "+f"(D[3])                     \
        : "r"(Av.x), "r"(Av.y), "r"(Av.z), "r"(Av.w), "r"(Bv.x), "r"(Bv.y))

// =====================================================================
// GEMM v8 (tensor-core, wide-N + pipelined): C[32][N] = A @ W^T, split-K.
// v7 (BN=128) was smem-bound: 24 LDS-wavefronts per 12 MMA (2.0 wf/MMA),
// tensor 26% / L1 68%, and serial LDG->STS staging (issue 25%). v8:
//   - BN=256, nt=4 per warp: the SAME 4 A-fragment LDS.128 feed 24 MMAs
//     per k16 -> 1.33 wf/MMA (33% smem traffic cut per FLOP).
//   - register prefetch of next k-step's W/A under the 48-MMA window.
// bf16 hi/lo split x 3 products, fp32 accum (rel err ~1e-5), fragment-
// ordered smem (v7-verified lane maps, nt widened).
// Block: 256 thr = 8 warps; tile M=32 x BN=256 x BK=32 per step.
// MODE 0: W = fused Wq(nope-compact rows)+Wkv virtual rows, -> g_p1.
// MODE 1: W = Wo, A = g_attn, -> g_p2.
// =====================================================================
template <int MODE>
__global__ void __launch_bounds__(256, 2) gemm_kernel(
    const float* __restrict__ A, const float* __restrict__ W0,
    const float* __restrict__ W1, int N, int ksteps, float* __restrict__ part) {
    // Wf[nt(32)][k16(2)][hl(2)][lane(32)][breg(2)] u32 = 8192 u32 (32 KB)
    // Af[mt(2)][k16(2)][hl(2)][lane(32)][areg(4)] u32 = 1024 u32 (4 KB)
    __shared__ __align__(16) unsigned Wf[8192];
    __shared__ __align__(16) unsigned Af[1024];

    const int t = threadIdx.x;
    const int w = t >> 5, l = t & 31;
    const int n0 = blockIdx.x * 256;
    const int kbase = blockIdx.y * (ksteps * 32);
    const float* Ap = (MODE == 0) ? A : g_attn;

    // ---- staging assignments (fixed n/m, k advances) ----
    // W: pass p (8 passes): n = p*32 + (t>>3), k-quad kk = (t&7)*4
    const int wn = t >> 3;
    const int wkk = (t & 7) * 4;
    const float* wptr[8];
#pragma unroll
    for (int p = 0; p < 8; p++) {
        int n = n0 + p * 32 + wn;
        const float* row;
        if (MODE == 0)
            row = (n < 4096) ? W0 + (size_t)((n >> 7) * 192 + (n & 127)) * HID
                             : W1 + (size_t)(n - 4096) * HID;
        else
            row = W0 + (size_t)n * HID;
        wptr[p] = row + kbase + wkk;
    }
    const int wk16 = wkk >> 4;
    const int wbreg = (wkk & 15) >> 3;
    const int wpidx = (wkk & 7) >> 1;
    // A: m = t>>3, same k-quad
    const int am = t >> 3;
    const float* aptr = Ap + (size_t)am * HID + kbase + wkk;
    const int amt = am >> 4;
    const int aareg = ((am >> 3) & 1) + 2 * wbreg;
    const int alane = 4 * (am & 7) + wpidx;

    float acc[2][4][4];   // [mt][j][c0..c3]
#pragma unroll
    for (int i = 0; i < 2; i++)
#pragma unroll
        for (int j = 0; j < 4; j++)
#pragma unroll
            for (int c = 0; c < 4; c++) acc[i][j][c] = 0.f;

    // prologue prefetch (step 0)
    float4 wv[8], av;
#pragma unroll
    for (int p = 0; p < 8; p++) wv[p] = *(const float4*)wptr[p];
    av = *(const float4*)aptr;

    for (int ks = 0; ks < ksteps; ks++) {
        __syncthreads();   // previous compute done before overwriting frags

        // ---- stage W from prefetched regs: convert + fragment-ordered STS ----
#pragma unroll
        for (int p = 0; p < 8; p++) {
            unsigned hi0, lo0, hi1, lo1;
            split2(wv[p].x, wv[p].y, hi0, lo0);
            split2(wv[p].z, wv[p].w, hi1, lo1);
            int n = p * 32 + wn;
            int nt = n >> 3;
            int lane0 = 4 * (n & 7) + wpidx;
            unsigned* baseh = Wf + (((nt * 2 + wk16) * 2 + 0) * 32) * 2 + wbreg;
            unsigned* basel = Wf + (((nt * 2 + wk16) * 2 + 1) * 32) * 2 + wbreg;
            baseh[lane0 * 2] = hi0;
            baseh[(lane0 + 1) * 2] = hi1;
            basel[lane0 * 2] = lo0;
            basel[(lane0 + 1) * 2] = lo1;
        }
        // ---- stage A ----
        {
            unsigned hi0, lo0, hi1, lo1;
            split2(av.x, av.y, hi0, lo0);
            split2(av.z, av.w, hi1, lo1);
            unsigned* baseh = Af + (((amt * 2 + wk16) * 2 + 0) * 32) * 4 + aareg;
            unsigned* basel = Af + (((amt * 2 + wk16) * 2 + 1) * 32) * 4 + aareg;
            baseh[alane * 4] = hi0;
            baseh[(alane + 1) * 4] = hi1;
            basel[alane * 4] = lo0;
            basel[(alane + 1) * 4] = lo1;
        }
        // ---- prefetch next step (hidden under compute) ----
        if (ks + 1 < ksteps) {
            const int kofs = (ks + 1) * 32;
#pragma unroll
            for (int p = 0; p < 8; p++)
                wv[p] = *(const float4*)(wptr[p] + kofs);
            av = *(const float4*)(aptr + kofs);
        }
        __syncthreads();

        // ---- compute: 2 k16 x (2 mt x 4 nt x 3 products) = 48 MMA ----
#pragma unroll
        for (int k16 = 0; k16 < 2; k16++) {
            uint4 Ah0 = *(const uint4*)(Af + (((0 * 2 + k16) * 2 + 0) * 32 + l) * 4);
            uint4 Al0 = *(const uint4*)(Af + (((0 * 2 + k16) * 2 + 1) * 32 + l) * 4);
            uint4 Ah1 = *(const uint4*)(Af + (((1 * 2 + k16) * 2 + 0) * 32 + l) * 4);
            uint4 Al1 = *(const uint4*)(Af + (((1 * 2 + k16) * 2 + 1) * 32 + l) * 4);
#pragma unroll
            for (int j = 0; j < 4; j++) {
                const int nt = 4 * w + j;
                uint2 Bh = *(const uint2*)(Wf + (((nt * 2 + k16) * 2 + 0) * 32 + l) * 2);
                uint2 Bl = *(const uint2*)(Wf + (((nt * 2 + k16) * 2 + 1) * 32 + l) * 2);
                MMA16816(acc[0][j], Ah0, Bh);
                MMA16816(acc[1][j], Ah1, Bh);
                MMA16816(acc[0][j], Al0, Bh);
                MMA16816(acc[1][j], Al1, Bh);
                MMA16816(acc[0][j], Ah0, Bl);
                MMA16816(acc[1][j], Ah1, Bl);
            }
        }
    }

    // ---- epilogue: C lane map: rows l/4, l/4+8; cols 2(l%4)+{0,1} ----
    float* pbase = part + (size_t)blockIdx.y * 32 * N;
#pragma unroll
    for (int mt = 0; mt < 2; mt++)
#pragma unroll
        for (int j = 0; j < 4; j++) {
            int col = n0 + w * 32 + j * 8 + 2 * (l & 3);
            int r0 = mt * 16 + (l >> 2);
            *(float2*)(pbase + (size_t)r0 * N + col) =
                make_float2(acc[mt][j][0], acc[mt][j][1]);
            *(float2*)(pbase + (size_t)(r0 + 8) * N + col) =
                make_float2(acc[mt][j][2], acc[mt][j][3]);
        }
}

// sum the SPLIT1 GEMM1 split-K partials -> g_qkv
__global__ void reduce_qkv_kernel() {
    int i = blockIdx.x * 256 + threadIdx.x;   // 393216 total
    float s = 0.f;
#pragma unroll
    for (int c = 0; c < SPLIT1; c++) s += g_p1[(size_t)c * 393216 + i];
    g_qkv[i] = s;
}

// =====================================================================
// Flash-decoding attention partial (AT THE MEMORY WALL: 80% DRAM, ~96%
// of the 6.35 TB/s LTS cap — unchanged). One block per (b,h,chunk).
// =====================================================================
__global__ void __launch_bounds__(256) attn_partial_kernel(
    const float* __restrict__ k_cache, const float* __restrict__ v_cache,
    const int* __restrict__ positions) {
    const int bh = blockIdx.x;
    const int c = blockIdx.y;
    const int b = bh >> 5, h = bh & 31;
    const int t = threadIdx.x, lane = t & 31, w = t >> 5;
    const int pos = positions[b];
    const int L = pos + 1;
    const int s0 = c * CHUNK;
    const int len = min(CHUNK, L - s0);
    const int pidx = bh * NCHUNK + c;
    if (len <= 0) return;   // g_pl pre-zeroed by prep kernel

    __shared__ float sc[CHUNK];
    __shared__ float red[256];
    __shared__ float redw[8];
    __shared__ float s_m, s_l;

    const float* qb = g_qkv + b * QKVN + h * 128;
    const float4 q4 = *(const float4*)(qb + lane * 4);
    const float* knew = g_qkv + b * QKVN + 4096 + h * 128;
    const float* kbasep = k_cache + (size_t)b * SS * (HH * 128) + h * 128;

    for (int sl = 4 * w; sl < len; sl += 32) {
        float4 kv[4];
        float dd[4];
#pragma unroll
        for (int i = 0; i < 4; i++) {
            int sli = sl + i;
            int s = s0 + sli;
            const float* kp = (sli < len)
                                  ? ((s == pos) ? knew
                                                : (kbasep + (size_t)s * 4096))
                                  : knew;   // safe dummy
            kv[i] = *(const float4*)(kp + lane * 4);
        }
#pragma unroll
        for (int i = 0; i < 4; i++)
            dd[i] = kv[i].x * q4.x + kv[i].y * q4.y + kv[i].z * q4.z +
                    kv[i].w * q4.w;
#pragma unroll
        for (int o = 16; o; o >>= 1) {
#pragma unroll
            for (int i = 0; i < 4; i++)
                dd[i] += __shfl_xor_sync(0xffffffffu, dd[i], o);
        }
        if (lane == 0) {
#pragma unroll
            for (int i = 0; i < 4; i++)
                if (sl + i < len) sc[sl + i] = dd[i] * SCALE;
        }
    }
    __syncthreads();

    float lm = (t < len) ? sc[t] : -1e30f;
#pragma unroll
    for (int o = 16; o; o >>= 1) lm = fmaxf(lm, __shfl_xor_sync(0xffffffffu, lm, o));
    if (lane == 0) redw[w] = lm;
    __syncthreads();
    if (t == 0) {
        float m = redw[0];
#pragma unroll
        for (int i = 1; i < 8; i++) m = fmaxf(m, redw[i]);
        s_m = m;
    }
    __syncthreads();
    const float m = s_m;
    float ls = 0.f;
    if (t < len) {
        float p = __expf(sc[t] - m);
        sc[t] = p;
        ls = p;
    }
#pragma unroll
    for (int o = 16; o; o >>= 1) ls += __shfl_xor_sync(0xffffffffu, ls, o);
    if (lane == 0) redw[w] = ls;
    __syncthreads();
    if (t == 0) {
        float l = 0.f;
#pragma unroll
        for (int i = 0; i < 8; i++) l += redw[i];
        s_l = l;
    }
    __syncthreads();

    const float* vnew = g_qkv + b * QKVN + 8192 + h * 128;
    const float* vbasep = v_cache + (size_t)b * SS * (HH * 128) + h * 128;
    const int d = t & 127;
    const int half = t >> 7;
    float acc = 0.f;
#pragma unroll 8
    for (int sl = half; sl < len; sl += 2) {
        int s = s0 + sl;
        const float* vr = (s == pos) ? vnew : (vbasep + (size_t)s * 4096);
        acc += sc[sl] * vr[d];
    }
    red[t] = acc;
    __syncthreads();
    if (t < 128) g_pacc[(size_t)pidx * 128 + t] = red[t] + red[t + 128];
    if (t == 0) {
        g_pm[pidx] = m;
        g_pl[pidx] = s_l;
    }
}

// combine the <=8 chunk partials per (b,h) -> g_attn[b][h*VD+d]
__global__ void __launch_bounds__(128) attn_combine_kernel() {
    const int bh = blockIdx.x;
    const int d = threadIdx.x;
    float M = -1e30f;
#pragma unroll
    for (int c = 0; c < NCHUNK; c++) {
        float l = g_pl[bh * NCHUNK + c];
        if (l > 0.f) M = fmaxf(M, g_pm[bh * NCHUNK + c]);
    }
    float L = 0.f, o = 0.f;
#pragma unroll
    for (int c = 0; c < NCHUNK; c++) {
        float l = g_pl[bh * NCHUNK + c];
        if (l > 0.f) {
            float wgt = __expf(g_pm[bh * NCHUNK + c] - M);
            L += l * wgt;
            o += g_pacc[(size_t)(bh * NCHUNK + c) * 128 + d] * wgt;
        }
    }
    const int b = bh >> 5, h = bh & 31;
    g_attn[b * 4096 + h * 128 + d] = o / L;
}

// sum the SPLIT2 GEMM2 split-K partials -> final output
__global__ void reduce_out_kernel(float* __restrict__ out) {
    int i = blockIdx.x * 256 + threadIdx.x;   // 131072 total
    float s = 0.f;
#pragma unroll
    for (int c = 0; c < SPLIT2; c++) s += g_p2[(size_t)c * 131072 + i];
    out[i] = s;
}

extern "C" void kernel_launch(void* const* d_in, const int* in_sizes, int n_in,
                              void* d_out, int out_size) {
    const float* hs = (const float*)d_in[0];
    const int* positions = (const int*)d_in[1];
    const float* k_cache = (const float*)d_in[2];
    const float* v_cache = (const float*)d_in[3];
    const float* Wq = (const float*)d_in[4];
    const float* Wkv = (const float*)d_in[5];
    const float* Wo = (const float*)d_in[6];
    float* out = (float*)d_out;

    float* p1;
    cudaGetSymbolAddress((void**)&p1, g_p1);
    float* p2;
    cudaGetSymbolAddress((void**)&p2, g_p2);

    // prep (slots 1-3): zero attention stats; puts gemm1 in profiled slot 4
    zero_pl_kernel<<<32, 256>>>();
    zero_pm0_kernel<<<16, 256>>>();
    zero_pm1_kernel<<<16, 256>>>();
    // 1) fused q(nope)/k/v projection: 48 N-tiles x split-K 16 (8 k-steps)
    gemm_kernel<0><<<dim3(48, SPLIT1), 256>>>(hs, Wq, Wkv, QKVN, 8, p1);
    reduce_qkv_kernel<<<1536, 256>>>();
    // 2) flash-decoding attention partials
    attn_partial_kernel<<<dim3(1024, NCHUNK), 256>>>(k_cache, v_cache, positions);
    attn_combine_kernel<<<1024, 128>>>();
    // 3) output projection: 16 N-tiles x split-K 16 (8 k-steps)
    gemm_kernel<1><<<dim3(16, SPLIT2), 256>>>(nullptr, Wo, nullptr, HID, 8, p2);
    reduce_out_kernel<<<512, 256>>>(out);
}